// round 9
// baseline (speedup 1.0000x reference)
#include <cuda_runtime.h>
#include <cuda_bf16.h>
#include <math.h>
#include <cstdint>

// Problem constants
#define BSZ 4
#define SEQ 4096
#define EMB 1024
#define HD  64
#define ROWS (BSZ * SEQ)

// KV-split chunking for attention
#define CH 8
#define MAXSEG 8
#define SEG_PER_BATCH 288

// Padded smem row stride: 72 bf16 = 144 bytes
#define SSTR 144

// ---------------------------------------------------------------------------
// Scratch (allocation-free: __device__ globals)
// ---------------------------------------------------------------------------
__device__ __nv_bfloat16 g_qh[ROWS * HD];   // Q * 2^-5, bf16 hi
__device__ __nv_bfloat16 g_ql[ROWS * HD];   // residual lo
__device__ __nv_bfloat16 g_kh[ROWS * HD];
__device__ __nv_bfloat16 g_kl[ROWS * HD];
__device__ __nv_bfloat16 g_vth[(size_t)BSZ * HD * SEQ];  // V^T: [b][h][token]
__device__ __nv_bfloat16 g_vtl[(size_t)BSZ * HD * SEQ];
__device__ __nv_bfloat16 g_wth[192 * EMB];  // W^T hi: [n(Q|K|V)][k]
__device__ __nv_bfloat16 g_wtl[192 * EMB];
__device__ float g_pacc[(size_t)BSZ * MAXSEG * SEQ * HD];
__device__ float g_pm[BSZ * MAXSEG * SEQ];
__device__ float g_pl[BSZ * MAXSEG * SEQ];

// ---------------------------------------------------------------------------
// Helpers
// ---------------------------------------------------------------------------
__device__ __forceinline__ uint32_t smem_u32(const void* p) {
    uint32_t a;
    asm("{ .reg .u64 t; cvta.to.shared.u64 t, %1; cvt.u32.u64 %0, t; }"
        : "=r"(a) : "l"(p));
    return a;
}
__device__ __forceinline__ void cp16(uint32_t dst_s, const void* src) {
    asm volatile("cp.async.cg.shared.global [%0], [%1], 16;\n" :: "r"(dst_s), "l"(src));
}
#define CP_COMMIT() asm volatile("cp.async.commit_group;\n" ::: "memory")
#define CP_WAIT0()  asm volatile("cp.async.wait_group 0;\n" ::: "memory")

// m16n8k16 bf16 MMA, fp32 accumulate in-place
__device__ __forceinline__ void mma_bf16(float* d, const uint32_t* a, const uint32_t* b) {
    asm volatile(
        "mma.sync.aligned.m16n8k16.row.col.f32.bf16.bf16.f32 "
        "{%0,%1,%2,%3}, {%4,%5,%6,%7}, {%8,%9}, {%0,%1,%2,%3};\n"
        : "+f"(d[0]), "+f"(d[1]), "+f"(d[2]), "+f"(d[3])
        : "r"(a[0]), "r"(a[1]), "r"(a[2]), "r"(a[3]), "r"(b[0]), "r"(b[1]));
}

// Split two floats into packed bf16x2 hi + packed bf16x2 lo
__device__ __forceinline__ void split2(float x0, float x1, uint32_t& hi, uint32_t& lo) {
    __nv_bfloat16 h0 = __float2bfloat16(x0);
    __nv_bfloat16 h1 = __float2bfloat16(x1);
    __nv_bfloat162 hh = __halves2bfloat162(h0, h1);
    hi = *(uint32_t*)&hh;
    __nv_bfloat162 ll = __floats2bfloat162_rn(x0 - __bfloat162float(h0),
                                              x1 - __bfloat162float(h1));
    lo = *(uint32_t*)&ll;
}

// ---------------------------------------------------------------------------
// Kernel 0: W^T -> bf16 hi/lo split. [192][1024]
// ---------------------------------------------------------------------------
__global__ __launch_bounds__(256) void wprep_kernel(
    const float* __restrict__ Wq, const float* __restrict__ Wk,
    const float* __restrict__ Wv)
{
    const int n = blockIdx.x;
    const int m = n >> 6;
    const int h = n & 63;
    const float* W = (m == 0) ? Wq : (m == 1) ? Wk : Wv;
    for (int k = threadIdx.x; k < EMB; k += 256) {
        float v = W[(size_t)k * HD + h];
        __nv_bfloat16 hi = __float2bfloat16(v);
        g_wth[(size_t)n * EMB + k] = hi;
        g_wtl[(size_t)n * EMB + k] = __float2bfloat16(v - __bfloat162float(hi));
    }
}

// ---------------------------------------------------------------------------
// Kernel 1: QKV projection via split-bf16 mma.sync.
// ONE change vs R8: W cp.async issued FIRST; x conversion overlaps flight.
// ---------------------------------------------------------------------------
#define XH_OFF 0
#define XL_OFF 9216
#define WH_OFF 18432
#define WL_OFF 46080
#define QKV_SM 73728

__global__ __launch_bounds__(256) void qkv_mma_kernel(const float* __restrict__ x)
{
    extern __shared__ char smc[];
    const uint32_t sb = smem_u32(smc);
    const int tid  = threadIdx.x;
    const int wid  = tid >> 5;
    const int lane = tid & 31;
    const int wr   = wid >> 1;
    const int wc   = wid & 1;
    const int r0   = blockIdx.x * 64;
    const int lq   = lane >> 2;
    const int lr   = lane & 3;

    float acc[12][4];
#pragma unroll
    for (int nt = 0; nt < 12; nt++)
#pragma unroll
        for (int q = 0; q < 4; q++) acc[nt][q] = 0.f;

    for (int c = 0; c < 16; c++) {
        const int k0 = c * 64;
        __syncthreads();   // previous chunk's consumers done

        // issue W^T chunk cp.async FIRST (flight hidden under x conversion)
#pragma unroll
        for (int it = 0; it < 6; it++) {
            int cid = tid + it * 256;
            int row = cid >> 3, g = cid & 7;
            size_t so = (size_t)row * EMB + k0 + g * 8;
            cp16(sb + WH_OFF + row * SSTR + g * 16, &g_wth[so]);
            cp16(sb + WL_OFF + row * SSTR + g * 16, &g_wtl[so]);
        }
        CP_COMMIT();

        // stage x chunk (fp32 -> bf16 hi/lo) while W is in flight
#pragma unroll
        for (int it = 0; it < 2; it++) {
            int cid = tid + it * 256;
            int row = cid >> 3, g = cid & 7;
            const float* src = x + (size_t)(r0 + row) * EMB + k0 + g * 8;
            float4 f0 = *(const float4*)src;
            float4 f1 = *(const float4*)(src + 4);
            uint32_t h[4], l[4];
            split2(f0.x, f0.y, h[0], l[0]);
            split2(f0.z, f0.w, h[1], l[1]);
            split2(f1.x, f1.y, h[2], l[2]);
            split2(f1.z, f1.w, h[3], l[3]);
            *(uint4*)(smc + XH_OFF + row * SSTR + g * 16) = *(uint4*)h;
            *(uint4*)(smc + XL_OFF + row * SSTR + g * 16) = *(uint4*)l;
        }

        CP_WAIT0();
        __syncthreads();

        // 4 k16 steps
#pragma unroll
        for (int ks = 0; ks < 4; ks++) {
            const int koff = ks * 32 + lr * 4;
            const int rowA = wr * 16 + lq;
            uint32_t aH[4], aL[4];
            aH[0] = *(const uint32_t*)(smc + XH_OFF + rowA * SSTR + koff);
            aH[1] = *(const uint32_t*)(smc + XH_OFF + (rowA + 8) * SSTR + koff);
            aH[2] = *(const uint32_t*)(smc + XH_OFF + rowA * SSTR + koff + 16);
            aH[3] = *(const uint32_t*)(smc + XH_OFF + (rowA + 8) * SSTR + koff + 16);
            aL[0] = *(const uint32_t*)(smc + XL_OFF + rowA * SSTR + koff);
            aL[1] = *(const uint32_t*)(smc + XL_OFF + (rowA + 8) * SSTR + koff);
            aL[2] = *(const uint32_t*)(smc + XL_OFF + rowA * SSTR + koff + 16);
            aL[3] = *(const uint32_t*)(smc + XL_OFF + (rowA + 8) * SSTR + koff + 16);
#pragma unroll
            for (int nt = 0; nt < 12; nt++) {
                int n = wc * 96 + nt * 8 + lq;
                const char* bp = smc + WH_OFF + n * SSTR + koff;
                const char* bq = smc + WL_OFF + n * SSTR + koff;
                uint32_t bH[2] = {*(const uint32_t*)bp, *(const uint32_t*)(bp + 16)};
                uint32_t bL[2] = {*(const uint32_t*)bq, *(const uint32_t*)(bq + 16)};
                mma_bf16(acc[nt], aH, bH);
                mma_bf16(acc[nt], aH, bL);
                mma_bf16(acc[nt], aL, bH);
            }
        }
    }

    // Epilogue: emit Q (scaled, split), K (split), V^T (split)
    const int rbase = r0 + wr * 16 + lq;
    const float scale = 0.03125f;  // exact power of 2
#pragma unroll
    for (int nt = 0; nt < 12; nt++) {
        int cc = wc * 96 + nt * 8 + lr * 2;
#pragma unroll
        for (int hh = 0; hh < 2; hh++) {
            int row = rbase + 8 * hh;
            float v0 = acc[nt][2 * hh], v1 = acc[nt][2 * hh + 1];
            if (cc < 64) {
                uint32_t hi, lo;
                split2(v0 * scale, v1 * scale, hi, lo);
                *(uint32_t*)&g_qh[(size_t)row * HD + cc] = hi;
                *(uint32_t*)&g_ql[(size_t)row * HD + cc] = lo;
            } else if (cc < 128) {
                uint32_t hi, lo;
                split2(v0, v1, hi, lo);
                *(uint32_t*)&g_kh[(size_t)row * HD + cc - 64] = hi;
                *(uint32_t*)&g_kl[(size_t)row * HD + cc - 64] = lo;
            } else {
                int h = cc - 128;
                int b = row >> 12;
                int tok = row & (SEQ - 1);
                size_t base = (size_t)b * HD * SEQ + tok;
                __nv_bfloat16 h0 = __float2bfloat16(v0);
                __nv_bfloat16 h1 = __float2bfloat16(v1);
                g_vth[base + (size_t)h * SEQ]       = h0;
                g_vth[base + (size_t)(h + 1) * SEQ] = h1;
                g_vtl[base + (size_t)h * SEQ]       = __float2bfloat16(v0 - __bfloat162float(h0));
                g_vtl[base + (size_t)(h + 1) * SEQ] = __float2bfloat16(v1 - __bfloat162float(h1));
            }
        }
    }
}

// ---------------------------------------------------------------------------
// Kernel 2: causal flash attention, split-KV, split-bf16 mma.sync
// (R8 structure, verbatim: single-buffered K/V, 3 CTAs/SM).
// ---------------------------------------------------------------------------
#define QH_OFF 0
#define QL_OFF 9216
#define KH_OFF 18432
#define KL_OFF 27648
#define VH_OFF 36864
#define VL_OFF 46080
#define ATTN_SM 55296

__global__ __launch_bounds__(128, 3) void attn_kernel()
{
    extern __shared__ char smc[];
    const uint32_t sb = smem_u32(smc);
    const int tid  = threadIdx.x;
    const int w    = tid >> 5;
    const int lane = tid & 31;
    const int lq   = lane >> 2;
    const int lr   = lane & 3;
    const int b    = blockIdx.y;

    // decode blockIdx.x -> (q-tile i, segment s)
    int fid = blockIdx.x;
    int i = 0, s = 0;
    {
        int accn = 0;
        for (int t = 63; t >= 0; t--) {
            int c = (t + CH) >> 3;
            if (fid < accn + c) { i = t; s = fid - accn; break; }
            accn += c;
        }
    }
    const int T  = i + 1;
    const int j0 = s * CH;
    const int j1 = (j0 + CH < T) ? (j0 + CH) : T;
    const int qr0 = i * 64;

    const size_t tok0  = (size_t)b * SEQ;
    const size_t vbase = (size_t)b * HD * SEQ;

    // stage Q (hi/lo) + first K/V tile
    {
        int kr0 = j0 * 64;
#pragma unroll
        for (int it = 0; it < 4; it++) {
            int cid = tid + it * 128;
            int row = cid >> 3, g = cid & 7;
            cp16(sb + QH_OFF + row * SSTR + g * 16, &g_qh[(tok0 + qr0 + row) * HD + g * 8]);
            cp16(sb + QL_OFF + row * SSTR + g * 16, &g_ql[(tok0 + qr0 + row) * HD + g * 8]);
            cp16(sb + KH_OFF + row * SSTR + g * 16, &g_kh[(tok0 + kr0 + row) * HD + g * 8]);
            cp16(sb + KL_OFF + row * SSTR + g * 16, &g_kl[(tok0 + kr0 + row) * HD + g * 8]);
            cp16(sb + VH_OFF + row * SSTR + g * 16, &g_vth[vbase + (size_t)row * SEQ + kr0 + g * 8]);
            cp16(sb + VL_OFF + row * SSTR + g * 16, &g_vtl[vbase + (size_t)row * SEQ + kr0 + g * 8]);
        }
    }
    CP_COMMIT();
    CP_WAIT0();
    __syncthreads();

    float O[8][4];
#pragma unroll
    for (int nt = 0; nt < 8; nt++)
#pragma unroll
        for (int q = 0; q < 4; q++) O[nt][q] = 0.f;
    float m0 = -1e30f, m1 = -1e30f, l0 = 0.f, l1 = 0.f;

    const char* Kh = smc + KH_OFF;
    const char* Kl = smc + KL_OFF;
    const char* Vh = smc + VH_OFF;
    const char* Vl = smc + VL_OFF;

    for (int j = j0; j < j1; j++) {
        // ---- S = Q K^T ----
        float S[8][4];
#pragma unroll
        for (int nt = 0; nt < 8; nt++)
#pragma unroll
            for (int q = 0; q < 4; q++) S[nt][q] = 0.f;

#pragma unroll
        for (int kf = 0; kf < 4; kf++) {
            const int koff = kf * 32 + lr * 4;
            const int rowA = w * 16 + lq;
            uint32_t aH[4], aL[4];
            aH[0] = *(const uint32_t*)(smc + QH_OFF + rowA * SSTR + koff);
            aH[1] = *(const uint32_t*)(smc + QH_OFF + (rowA + 8) * SSTR + koff);
            aH[2] = *(const uint32_t*)(smc + QH_OFF + rowA * SSTR + koff + 16);
            aH[3] = *(const uint32_t*)(smc + QH_OFF + (rowA + 8) * SSTR + koff + 16);
            aL[0] = *(const uint32_t*)(smc + QL_OFF + rowA * SSTR + koff);
            aL[1] = *(const uint32_t*)(smc + QL_OFF + (rowA + 8) * SSTR + koff);
            aL[2] = *(const uint32_t*)(smc + QL_OFF + rowA * SSTR + koff + 16);
            aL[3] = *(const uint32_t*)(smc + QL_OFF + (rowA + 8) * SSTR + koff + 16);
#pragma unroll
            for (int nt = 0; nt < 8; nt++) {
                int key = nt * 8 + lq;
                const char* bp = Kh + key * SSTR + koff;
                const char* bq = Kl + key * SSTR + koff;
                uint32_t bH[2] = {*(const uint32_t*)bp, *(const uint32_t*)(bp + 16)};
                uint32_t bL[2] = {*(const uint32_t*)bq, *(const uint32_t*)(bq + 16)};
                mma_bf16(S[nt], aH, bH);
                mma_bf16(S[nt], aH, bL);
                mma_bf16(S[nt], aL, bH);
            }
        }

        // causal mask (diagonal tile only)
        if (j == i) {
            int r0g = w * 16 + lq;
#pragma unroll
            for (int nt = 0; nt < 8; nt++) {
                int c0 = nt * 8 + lr * 2;
                if (c0 > r0g)         S[nt][0] = -1e30f;
                if (c0 + 1 > r0g)     S[nt][1] = -1e30f;
                if (c0 > r0g + 8)     S[nt][2] = -1e30f;
                if (c0 + 1 > r0g + 8) S[nt][3] = -1e30f;
            }
        }

        // ---- online softmax ----
        float mn0 = -1e30f, mn1 = -1e30f;
#pragma unroll
        for (int nt = 0; nt < 8; nt++) {
            mn0 = fmaxf(mn0, fmaxf(S[nt][0], S[nt][1]));
            mn1 = fmaxf(mn1, fmaxf(S[nt][2], S[nt][3]));
        }
        mn0 = fmaxf(mn0, __shfl_xor_sync(0xffffffffu, mn0, 1));
        mn0 = fmaxf(mn0, __shfl_xor_sync(0xffffffffu, mn0, 2));
        mn1 = fmaxf(mn1, __shfl_xor_sync(0xffffffffu, mn1, 1));
        mn1 = fmaxf(mn1, __shfl_xor_sync(0xffffffffu, mn1, 2));
        float mc0 = fmaxf(m0, mn0), mc1 = fmaxf(m1, mn1);
        float al0 = __expf(m0 - mc0), al1 = __expf(m1 - mc1);
        m0 = mc0; m1 = mc1;
        float rs0 = 0.f, rs1 = 0.f;
#pragma unroll
        for (int nt = 0; nt < 8; nt++) {
            S[nt][0] = __expf(S[nt][0] - mc0);
            S[nt][1] = __expf(S[nt][1] - mc0);
            S[nt][2] = __expf(S[nt][2] - mc1);
            S[nt][3] = __expf(S[nt][3] - mc1);
            rs0 += S[nt][0] + S[nt][1];
            rs1 += S[nt][2] + S[nt][3];
        }
        rs0 += __shfl_xor_sync(0xffffffffu, rs0, 1);
        rs0 += __shfl_xor_sync(0xffffffffu, rs0, 2);
        rs1 += __shfl_xor_sync(0xffffffffu, rs1, 1);
        rs1 += __shfl_xor_sync(0xffffffffu, rs1, 2);
        l0 = l0 * al0 + rs0;
        l1 = l1 * al1 + rs1;
#pragma unroll
        for (int nt = 0; nt < 8; nt++) {
            O[nt][0] *= al0; O[nt][1] *= al0;
            O[nt][2] *= al1; O[nt][3] *= al1;
        }

        // ---- O += P V (P re-packed from S frags, split hi/lo) ----
#pragma unroll
        for (int kf = 0; kf < 4; kf++) {
            uint32_t aPh[4], aPl[4];
            split2(S[2 * kf][0],     S[2 * kf][1],     aPh[0], aPl[0]);
            split2(S[2 * kf][2],     S[2 * kf][3],     aPh[1], aPl[1]);
            split2(S[2 * kf + 1][0], S[2 * kf + 1][1], aPh[2], aPl[2]);
            split2(S[2 * kf + 1][2], S[2 * kf + 1][3], aPh[3], aPl[3]);
            const int koff = kf * 32 + lr * 4;
#pragma unroll
            for (int nt = 0; nt < 8; nt++) {
                int h = nt * 8 + lq;
                const char* bp = Vh + h * SSTR + koff;
                const char* bq = Vl + h * SSTR + koff;
                uint32_t bH[2] = {*(const uint32_t*)bp, *(const uint32_t*)(bp + 16)};
                uint32_t bL[2] = {*(const uint32_t*)bq, *(const uint32_t*)(bq + 16)};
                mma_bf16(O[nt], aPh, bH);
                mma_bf16(O[nt], aPh, bL);
                mma_bf16(O[nt], aPl, bH);
            }
        }

        // load next tile into the (single) buffer
        if (j + 1 < j1) {
            __syncthreads();   // all warps done reading K/V
            int kr0 = (j + 1) * 64;
#pragma unroll
            for (int it = 0; it < 4; it++) {
                int cid = tid + it * 128;
                int row = cid >> 3, g = cid & 7;
                cp16(sb + KH_OFF + row * SSTR + g * 16, &g_kh[(tok0 + kr0 + row) * HD + g * 8]);
                cp16(sb + KL_OFF + row * SSTR + g * 16, &g_kl[(tok0 + kr0 + row) * HD + g * 8]);
                cp16(sb + VH_OFF + row * SSTR + g * 16, &g_vth[vbase + (size_t)row * SEQ + kr0 + g * 8]);
                cp16(sb + VL_OFF + row * SSTR + g * 16, &g_vtl[vbase + (size_t)row * SEQ + kr0 + g * 8]);
            }
            CP_COMMIT();
            CP_WAIT0();
            __syncthreads();   // new data visible to all warps
        }
    }

    // Epilogue: unnormalized partials + (m, l)
    const size_t segrow = ((size_t)b * MAXSEG + s) * SEQ + qr0 + w * 16 + lq;
#pragma unroll
    for (int nt = 0; nt < 8; nt++) {
        int cc = nt * 8 + lr * 2;
        *(float2*)&g_pacc[segrow * HD + cc] = make_float2(O[nt][0], O[nt][1]);
        *(float2*)&g_pacc[(segrow + 8) * HD + cc] = make_float2(O[nt][2], O[nt][3]);
    }
    if (lr == 0) {
        g_pm[segrow] = m0;     g_pl[segrow] = l0;
        g_pm[segrow + 8] = m1; g_pl[segrow + 8] = l1;
    }
}

// ---------------------------------------------------------------------------
// Kernel 3: combine split-KV partials and normalize.
// 2 independent float4 chains per thread (double MLP).
// Block = 256 threads = 32 rows x 8 col-groups; each thread does c4 and c4+32.
// Grid = (SEQ/32, B).
// ---------------------------------------------------------------------------
__global__ __launch_bounds__(256) void combine_kernel(float* __restrict__ out)
{
    const int b   = blockIdx.y;
    const int row = blockIdx.x * 32 + (threadIdx.x >> 3);
    const int c4  = (threadIdx.x & 7) * 4;
    const int i   = row >> 6;
    const int nseg = (i + CH) >> 3;

    const size_t base = (size_t)b * MAXSEG * SEQ + row;

    float M = -1e30f;
#pragma unroll 4
    for (int s = 0; s < nseg; s++)
        M = fmaxf(M, g_pm[base + (size_t)s * SEQ]);

    float L = 0.f;
    float a0x = 0.f, a0y = 0.f, a0z = 0.f, a0w = 0.f;
    float a1x = 0.f, a1y = 0.f, a1z = 0.f, a1w = 0.f;
#pragma unroll 4
    for (int s = 0; s < nseg; s++) {
        size_t idx = base + (size_t)s * SEQ;
        float wgt = __expf(g_pm[idx] - M);
        L = fmaf(wgt, g_pl[idx], L);
        float4 p0 = *(const float4*)&g_pacc[idx * HD + c4];
        float4 p1 = *(const float4*)&g_pacc[idx * HD + c4 + 32];
        a0x = fmaf(wgt, p0.x, a0x); a0y = fmaf(wgt, p0.y, a0y);
        a0z = fmaf(wgt, p0.z, a0z); a0w = fmaf(wgt, p0.w, a0w);
        a1x = fmaf(wgt, p1.x, a1x); a1y = fmaf(wgt, p1.y, a1y);
        a1z = fmaf(wgt, p1.z, a1z); a1w = fmaf(wgt, p1.w, a1w);
    }

    const float inv = 1.f / L;
    const size_t obase = ((size_t)b * SEQ + row) * HD;
    *(float4*)&out[obase + c4] =
        make_float4(a0x * inv, a0y * inv, a0z * inv, a0w * inv);
    *(float4*)&out[obase + c4 + 32] =
        make_float4(a1x * inv, a1y * inv, a1z * inv, a1w * inv);
}

// ---------------------------------------------------------------------------
// Launch: inputs in metadata order x, Wk, Wq, Wv. Output [B,S,H] fp32.
// ---------------------------------------------------------------------------
extern "C" void kernel_launch(void* const* d_in, const int* in_sizes, int n_in,
                              void* d_out, int out_size)
{
    const float* x  = (const float*)d_in[0];
    const float* Wk = (const float*)d_in[1];
    const float* Wq = (const float*)d_in[2];
    const float* Wv = (const float*)d_in[3];
    float* out = (float*)d_out;

    wprep_kernel<<<192, 256>>>(Wq, Wk, Wv);

    cudaFuncSetAttribute(qkv_mma_kernel,
                         cudaFuncAttributeMaxDynamicSharedMemorySize, QKV_SM);
    qkv_mma_kernel<<<ROWS / 64, 256, QKV_SM>>>(x);

    cudaFuncSetAttribute(attn_kernel,
                         cudaFuncAttributeMaxDynamicSharedMemorySize, ATTN_SM);
    attn_kernel<<<dim3(SEG_PER_BATCH, BSZ), 128, ATTN_SM>>>();

    combine_kernel<<<dim3(SEQ / 32, BSZ), 256>>>(out);
}

// round 10
// speedup vs baseline: 1.0383x; 1.0383x over previous
#include <cuda_runtime.h>
#include <cuda_bf16.h>
#include <math.h>
#include <cstdint>

// Problem constants
#define BSZ 4
#define SEQ 4096
#define EMB 1024
#define HD  64
#define ROWS (BSZ * SEQ)

// KV-split chunking for attention
#define CH 8
#define MAXSEG 8
#define SEG_PER_BATCH 288

// Padded smem row stride: 72 bf16 = 144 bytes
#define SSTR 144

// ---------------------------------------------------------------------------
// Scratch (allocation-free: __device__ globals)
// ---------------------------------------------------------------------------
__device__ __nv_bfloat16 g_qh[ROWS * HD];   // Q * 2^-5, bf16 hi
__device__ __nv_bfloat16 g_ql[ROWS * HD];   // residual lo
__device__ __nv_bfloat16 g_kh[ROWS * HD];
__device__ __nv_bfloat16 g_kl[ROWS * HD];
__device__ __nv_bfloat16 g_vth[(size_t)BSZ * HD * SEQ];  // V^T: [b][h][token]
__device__ __nv_bfloat16 g_vtl[(size_t)BSZ * HD * SEQ];
__device__ __nv_bfloat16 g_wth[192 * EMB];  // W^T hi: [n(Q|K|V)][k]
__device__ __nv_bfloat16 g_wtl[192 * EMB];
__device__ float g_pacc[(size_t)BSZ * MAXSEG * SEQ * HD];
__device__ float g_pm[BSZ * MAXSEG * SEQ];
__device__ float g_pl[BSZ * MAXSEG * SEQ];

// ---------------------------------------------------------------------------
// Helpers
// ---------------------------------------------------------------------------
__device__ __forceinline__ uint32_t smem_u32(const void* p) {
    uint32_t a;
    asm("{ .reg .u64 t; cvta.to.shared.u64 t, %1; cvt.u32.u64 %0, t; }"
        : "=r"(a) : "l"(p));
    return a;
}
__device__ __forceinline__ void cp16(uint32_t dst_s, const void* src) {
    asm volatile("cp.async.cg.shared.global [%0], [%1], 16;\n" :: "r"(dst_s), "l"(src));
}
#define CP_COMMIT() asm volatile("cp.async.commit_group;\n" ::: "memory")
#define CP_WAIT0()  asm volatile("cp.async.wait_group 0;\n" ::: "memory")

// m16n8k16 bf16 MMA, fp32 accumulate in-place
__device__ __forceinline__ void mma_bf16(float* d, const uint32_t* a, const uint32_t* b) {
    asm volatile(
        "mma.sync.aligned.m16n8k16.row.col.f32.bf16.bf16.f32 "
        "{%0,%1,%2,%3}, {%4,%5,%6,%7}, {%8,%9}, {%0,%1,%2,%3};\n"
        : "+f"(d[0]), "+f"(d[1]), "+f"(d[2]), "+f"(d[3])
        : "r"(a[0]), "r"(a[1]), "r"(a[2]), "r"(a[3]), "r"(b[0]), "r"(b[1]));
}

// ldmatrix x4: four 8x8 b16 matrices, row addresses from lanes 0-31
__device__ __forceinline__ void ldsm_x4(uint32_t& d0, uint32_t& d1,
                                        uint32_t& d2, uint32_t& d3, uint32_t addr) {
    asm volatile("ldmatrix.sync.aligned.m8n8.x4.shared.b16 {%0,%1,%2,%3}, [%4];"
        : "=r"(d0), "=r"(d1), "=r"(d2), "=r"(d3) : "r"(addr));
}

// Split two floats into packed bf16x2 hi + packed bf16x2 lo
__device__ __forceinline__ void split2(float x0, float x1, uint32_t& hi, uint32_t& lo) {
    __nv_bfloat16 h0 = __float2bfloat16(x0);
    __nv_bfloat16 h1 = __float2bfloat16(x1);
    __nv_bfloat162 hh = __halves2bfloat162(h0, h1);
    hi = *(uint32_t*)&hh;
    __nv_bfloat162 ll = __floats2bfloat162_rn(x0 - __bfloat162float(h0),
                                              x1 - __bfloat162float(h1));
    lo = *(uint32_t*)&ll;
}

// ---------------------------------------------------------------------------
// Kernel 0: W^T -> bf16 hi/lo split. [192][1024]
// ---------------------------------------------------------------------------
__global__ __launch_bounds__(256) void wprep_kernel(
    const float* __restrict__ Wq, const float* __restrict__ Wk,
    const float* __restrict__ Wv)
{
    const int n = blockIdx.x;
    const int m = n >> 6;
    const int h = n & 63;
    const float* W = (m == 0) ? Wq : (m == 1) ? Wk : Wv;
    for (int k = threadIdx.x; k < EMB; k += 256) {
        float v = W[(size_t)k * HD + h];
        __nv_bfloat16 hi = __float2bfloat16(v);
        g_wth[(size_t)n * EMB + k] = hi;
        g_wtl[(size_t)n * EMB + k] = __float2bfloat16(v - __bfloat162float(hi));
    }
}

// ---------------------------------------------------------------------------
// Kernel 1: QKV projection via split-bf16 mma.sync (R8 structure, verbatim).
// ---------------------------------------------------------------------------
#define XH_OFF 0
#define XL_OFF 9216
#define WH_OFF 18432
#define WL_OFF 46080
#define QKV_SM 73728

__global__ __launch_bounds__(256) void qkv_mma_kernel(const float* __restrict__ x)
{
    extern __shared__ char smc[];
    const uint32_t sb = smem_u32(smc);
    const int tid  = threadIdx.x;
    const int wid  = tid >> 5;
    const int lane = tid & 31;
    const int wr   = wid >> 1;
    const int wc   = wid & 1;
    const int r0   = blockIdx.x * 64;
    const int lq   = lane >> 2;
    const int lr   = lane & 3;

    float acc[12][4];
#pragma unroll
    for (int nt = 0; nt < 12; nt++)
#pragma unroll
        for (int q = 0; q < 4; q++) acc[nt][q] = 0.f;

    for (int c = 0; c < 16; c++) {
        const int k0 = c * 64;
        __syncthreads();   // previous chunk's consumers done

        // stage x chunk (fp32 -> bf16 hi/lo)
#pragma unroll
        for (int it = 0; it < 2; it++) {
            int cid = tid + it * 256;
            int row = cid >> 3, g = cid & 7;
            const float* src = x + (size_t)(r0 + row) * EMB + k0 + g * 8;
            float4 f0 = *(const float4*)src;
            float4 f1 = *(const float4*)(src + 4);
            uint32_t h[4], l[4];
            split2(f0.x, f0.y, h[0], l[0]);
            split2(f0.z, f0.w, h[1], l[1]);
            split2(f1.x, f1.y, h[2], l[2]);
            split2(f1.z, f1.w, h[3], l[3]);
            *(uint4*)(smc + XH_OFF + row * SSTR + g * 16) = *(uint4*)h;
            *(uint4*)(smc + XL_OFF + row * SSTR + g * 16) = *(uint4*)l;
        }
        // stage W^T chunk via cp.async
#pragma unroll
        for (int it = 0; it < 6; it++) {
            int cid = tid + it * 256;
            int row = cid >> 3, g = cid & 7;
            size_t so = (size_t)row * EMB + k0 + g * 8;
            cp16(sb + WH_OFF + row * SSTR + g * 16, &g_wth[so]);
            cp16(sb + WL_OFF + row * SSTR + g * 16, &g_wtl[so]);
        }
        CP_COMMIT();
        CP_WAIT0();
        __syncthreads();

        // 4 k16 steps
#pragma unroll
        for (int ks = 0; ks < 4; ks++) {
            const int koff = ks * 32 + lr * 4;
            const int rowA = wr * 16 + lq;
            uint32_t aH[4], aL[4];
            aH[0] = *(const uint32_t*)(smc + XH_OFF + rowA * SSTR + koff);
            aH[1] = *(const uint32_t*)(smc + XH_OFF + (rowA + 8) * SSTR + koff);
            aH[2] = *(const uint32_t*)(smc + XH_OFF + rowA * SSTR + koff + 16);
            aH[3] = *(const uint32_t*)(smc + XH_OFF + (rowA + 8) * SSTR + koff + 16);
            aL[0] = *(const uint32_t*)(smc + XL_OFF + rowA * SSTR + koff);
            aL[1] = *(const uint32_t*)(smc + XL_OFF + (rowA + 8) * SSTR + koff);
            aL[2] = *(const uint32_t*)(smc + XL_OFF + rowA * SSTR + koff + 16);
            aL[3] = *(const uint32_t*)(smc + XL_OFF + (rowA + 8) * SSTR + koff + 16);
#pragma unroll
            for (int nt = 0; nt < 12; nt++) {
                int n = wc * 96 + nt * 8 + lq;
                const char* bp = smc + WH_OFF + n * SSTR + koff;
                const char* bq = smc + WL_OFF + n * SSTR + koff;
                uint32_t bH[2] = {*(const uint32_t*)bp, *(const uint32_t*)(bp + 16)};
                uint32_t bL[2] = {*(const uint32_t*)bq, *(const uint32_t*)(bq + 16)};
                mma_bf16(acc[nt], aH, bH);
                mma_bf16(acc[nt], aH, bL);
                mma_bf16(acc[nt], aL, bH);
            }
        }
    }

    // Epilogue: emit Q (scaled, split), K (split), V^T (split)
    const int rbase = r0 + wr * 16 + lq;
    const float scale = 0.03125f;  // exact power of 2
#pragma unroll
    for (int nt = 0; nt < 12; nt++) {
        int cc = wc * 96 + nt * 8 + lr * 2;
#pragma unroll
        for (int hh = 0; hh < 2; hh++) {
            int row = rbase + 8 * hh;
            float v0 = acc[nt][2 * hh], v1 = acc[nt][2 * hh + 1];
            if (cc < 64) {
                uint32_t hi, lo;
                split2(v0 * scale, v1 * scale, hi, lo);
                *(uint32_t*)&g_qh[(size_t)row * HD + cc] = hi;
                *(uint32_t*)&g_ql[(size_t)row * HD + cc] = lo;
            } else if (cc < 128) {
                uint32_t hi, lo;
                split2(v0, v1, hi, lo);
                *(uint32_t*)&g_kh[(size_t)row * HD + cc - 64] = hi;
                *(uint32_t*)&g_kl[(size_t)row * HD + cc - 64] = lo;
            } else {
                int h = cc - 128;
                int b = row >> 12;
                int tok = row & (SEQ - 1);
                size_t base = (size_t)b * HD * SEQ + tok;
                __nv_bfloat16 h0 = __float2bfloat16(v0);
                __nv_bfloat16 h1 = __float2bfloat16(v1);
                g_vth[base + (size_t)h * SEQ]       = h0;
                g_vth[base + (size_t)(h + 1) * SEQ] = h1;
                g_vtl[base + (size_t)h * SEQ]       = __float2bfloat16(v0 - __bfloat162float(h0));
                g_vtl[base + (size_t)(h + 1) * SEQ] = __float2bfloat16(v1 - __bfloat162float(h1));
            }
        }
    }
}

// ---------------------------------------------------------------------------
// Kernel 2: causal flash attention, split-KV, split-bf16 mma.sync.
// R8 structure (single-buffered K/V, 3 CTAs/SM); ONE change: K/V B-fragments
// loaded via ldmatrix.x4 (2 nt-groups per instruction) instead of 4x LDS.b32.
// ---------------------------------------------------------------------------
#define QH_OFF 0
#define QL_OFF 9216
#define KH_OFF 18432
#define KL_OFF 27648
#define VH_OFF 36864
#define VL_OFF 46080
#define ATTN_SM 55296

__global__ __launch_bounds__(128, 3) void attn_kernel()
{
    extern __shared__ char smc[];
    const uint32_t sb = smem_u32(smc);
    const int tid  = threadIdx.x;
    const int w    = tid >> 5;
    const int lane = tid & 31;
    const int lq   = lane >> 2;
    const int lr   = lane & 3;
    const int b    = blockIdx.y;

    // ldmatrix lane mapping: matrix idx = lane>>3
    //   mrow: row offset within the 16-row group (0-7 for mats 0/1, 8-15 for 2/3)
    //   mkb : byte offset selecting k-block (0 for mats 0/2, 16 for mats 1/3)
    const int mrow = ((lane >> 4) << 3) + (lane & 7);
    const int mkb  = ((lane >> 3) & 1) << 4;

    // decode blockIdx.x -> (q-tile i, segment s)
    int fid = blockIdx.x;
    int i = 0, s = 0;
    {
        int accn = 0;
        for (int t = 63; t >= 0; t--) {
            int c = (t + CH) >> 3;
            if (fid < accn + c) { i = t; s = fid - accn; break; }
            accn += c;
        }
    }
    const int T  = i + 1;
    const int j0 = s * CH;
    const int j1 = (j0 + CH < T) ? (j0 + CH) : T;
    const int qr0 = i * 64;

    const size_t tok0  = (size_t)b * SEQ;
    const size_t vbase = (size_t)b * HD * SEQ;

    // stage Q (hi/lo) + first K/V tile
    {
        int kr0 = j0 * 64;
#pragma unroll
        for (int it = 0; it < 4; it++) {
            int cid = tid + it * 128;
            int row = cid >> 3, g = cid & 7;
            cp16(sb + QH_OFF + row * SSTR + g * 16, &g_qh[(tok0 + qr0 + row) * HD + g * 8]);
            cp16(sb + QL_OFF + row * SSTR + g * 16, &g_ql[(tok0 + qr0 + row) * HD + g * 8]);
            cp16(sb + KH_OFF + row * SSTR + g * 16, &g_kh[(tok0 + kr0 + row) * HD + g * 8]);
            cp16(sb + KL_OFF + row * SSTR + g * 16, &g_kl[(tok0 + kr0 + row) * HD + g * 8]);
            cp16(sb + VH_OFF + row * SSTR + g * 16, &g_vth[vbase + (size_t)row * SEQ + kr0 + g * 8]);
            cp16(sb + VL_OFF + row * SSTR + g * 16, &g_vtl[vbase + (size_t)row * SEQ + kr0 + g * 8]);
        }
    }
    CP_COMMIT();
    CP_WAIT0();
    __syncthreads();

    float O[8][4];
#pragma unroll
    for (int nt = 0; nt < 8; nt++)
#pragma unroll
        for (int q = 0; q < 4; q++) O[nt][q] = 0.f;
    float m0 = -1e30f, m1 = -1e30f, l0 = 0.f, l1 = 0.f;

    for (int j = j0; j < j1; j++) {
        // ---- S = Q K^T ----
        float S[8][4];
#pragma unroll
        for (int nt = 0; nt < 8; nt++)
#pragma unroll
            for (int q = 0; q < 4; q++) S[nt][q] = 0.f;

#pragma unroll
        for (int kf = 0; kf < 4; kf++) {
            const int koff = kf * 32 + lr * 4;
            const int kfb  = kf * 32;
            const int rowA = w * 16 + lq;
            uint32_t aH[4], aL[4];
            aH[0] = *(const uint32_t*)(smc + QH_OFF + rowA * SSTR + koff);
            aH[1] = *(const uint32_t*)(smc + QH_OFF + (rowA + 8) * SSTR + koff);
            aH[2] = *(const uint32_t*)(smc + QH_OFF + rowA * SSTR + koff + 16);
            aH[3] = *(const uint32_t*)(smc + QH_OFF + (rowA + 8) * SSTR + koff + 16);
            aL[0] = *(const uint32_t*)(smc + QL_OFF + rowA * SSTR + koff);
            aL[1] = *(const uint32_t*)(smc + QL_OFF + (rowA + 8) * SSTR + koff);
            aL[2] = *(const uint32_t*)(smc + QL_OFF + rowA * SSTR + koff + 16);
            aL[3] = *(const uint32_t*)(smc + QL_OFF + (rowA + 8) * SSTR + koff + 16);
#pragma unroll
            for (int nt2 = 0; nt2 < 4; nt2++) {
                uint32_t rowb = (uint32_t)((nt2 * 16 + mrow) * SSTR + kfb + mkb);
                uint32_t bHa[2], bHb[2], bLa[2], bLb[2];
                ldsm_x4(bHa[0], bHa[1], bHb[0], bHb[1], sb + KH_OFF + rowb);
                ldsm_x4(bLa[0], bLa[1], bLb[0], bLb[1], sb + KL_OFF + rowb);
                mma_bf16(S[nt2 * 2],     aH, bHa);
                mma_bf16(S[nt2 * 2],     aH, bLa);
                mma_bf16(S[nt2 * 2],     aL, bHa);
                mma_bf16(S[nt2 * 2 + 1], aH, bHb);
                mma_bf16(S[nt2 * 2 + 1], aH, bLb);
                mma_bf16(S[nt2 * 2 + 1], aL, bHb);
            }
        }

        // causal mask (diagonal tile only)
        if (j == i) {
            int r0g = w * 16 + lq;
#pragma unroll
            for (int nt = 0; nt < 8; nt++) {
                int c0 = nt * 8 + lr * 2;
                if (c0 > r0g)         S[nt][0] = -1e30f;
                if (c0 + 1 > r0g)     S[nt][1] = -1e30f;
                if (c0 > r0g + 8)     S[nt][2] = -1e30f;
                if (c0 + 1 > r0g + 8) S[nt][3] = -1e30f;
            }
        }

        // ---- online softmax ----
        float mn0 = -1e30f, mn1 = -1e30f;
#pragma unroll
        for (int nt = 0; nt < 8; nt++) {
            mn0 = fmaxf(mn0, fmaxf(S[nt][0], S[nt][1]));
            mn1 = fmaxf(mn1, fmaxf(S[nt][2], S[nt][3]));
        }
        mn0 = fmaxf(mn0, __shfl_xor_sync(0xffffffffu, mn0, 1));
        mn0 = fmaxf(mn0, __shfl_xor_sync(0xffffffffu, mn0, 2));
        mn1 = fmaxf(mn1, __shfl_xor_sync(0xffffffffu, mn1, 1));
        mn1 = fmaxf(mn1, __shfl_xor_sync(0xffffffffu, mn1, 2));
        float mc0 = fmaxf(m0, mn0), mc1 = fmaxf(m1, mn1);
        float al0 = __expf(m0 - mc0), al1 = __expf(m1 - mc1);
        m0 = mc0; m1 = mc1;
        float rs0 = 0.f, rs1 = 0.f;
#pragma unroll
        for (int nt = 0; nt < 8; nt++) {
            S[nt][0] = __expf(S[nt][0] - mc0);
            S[nt][1] = __expf(S[nt][1] - mc0);
            S[nt][2] = __expf(S[nt][2] - mc1);
            S[nt][3] = __expf(S[nt][3] - mc1);
            rs0 += S[nt][0] + S[nt][1];
            rs1 += S[nt][2] + S[nt][3];
        }
        rs0 += __shfl_xor_sync(0xffffffffu, rs0, 1);
        rs0 += __shfl_xor_sync(0xffffffffu, rs0, 2);
        rs1 += __shfl_xor_sync(0xffffffffu, rs1, 1);
        rs1 += __shfl_xor_sync(0xffffffffu, rs1, 2);
        l0 = l0 * al0 + rs0;
        l1 = l1 * al1 + rs1;
#pragma unroll
        for (int nt = 0; nt < 8; nt++) {
            O[nt][0] *= al0; O[nt][1] *= al0;
            O[nt][2] *= al1; O[nt][3] *= al1;
        }

        // ---- O += P V (P re-packed from S frags; V B-frags via ldmatrix) ----
#pragma unroll
        for (int kf = 0; kf < 4; kf++) {
            uint32_t aPh[4], aPl[4];
            split2(S[2 * kf][0],     S[2 * kf][1],     aPh[0], aPl[0]);
            split2(S[2 * kf][2],     S[2 * kf][3],     aPh[1], aPl[1]);
            split2(S[2 * kf + 1][0], S[2 * kf + 1][1], aPh[2], aPl[2]);
            split2(S[2 * kf + 1][2], S[2 * kf + 1][3], aPh[3], aPl[3]);
            const int kfb = kf * 32;
#pragma unroll
            for (int nt2 = 0; nt2 < 4; nt2++) {
                uint32_t rowb = (uint32_t)((nt2 * 16 + mrow) * SSTR + kfb + mkb);
                uint32_t bHa[2], bHb[2], bLa[2], bLb[2];
                ldsm_x4(bHa[0], bHa[1], bHb[0], bHb[1], sb + VH_OFF + rowb);
                ldsm_x4(bLa[0], bLa[1], bLb[0], bLb[1], sb + VL_OFF + rowb);
                mma_bf16(O[nt2 * 2],     aPh, bHa);
                mma_bf16(O[nt2 * 2],     aPh, bLa);
                mma_bf16(O[nt2 * 2],     aPl, bHa);
                mma_bf16(O[nt2 * 2 + 1], aPh, bHb);
                mma_bf16(O[nt2 * 2 + 1], aPh, bLb);
                mma_bf16(O[nt2 * 2 + 1], aPl, bHb);
            }
        }

        // load next tile into the (single) buffer
        if (j + 1 < j1) {
            __syncthreads();   // all warps done reading K/V
            int kr0 = (j + 1) * 64;
#pragma unroll
            for (int it = 0; it < 4; it++) {
                int cid = tid + it * 128;
                int row = cid >> 3, g = cid & 7;
                cp16(sb + KH_OFF + row * SSTR + g * 16, &g_kh[(tok0 + kr0 + row) * HD + g * 8]);
                cp16(sb + KL_OFF + row * SSTR + g * 16, &g_kl[(tok0 + kr0 + row) * HD + g * 8]);
                cp16(sb + VH_OFF + row * SSTR + g * 16, &g_vth[vbase + (size_t)row * SEQ + kr0 + g * 8]);
                cp16(sb + VL_OFF + row * SSTR + g * 16, &g_vtl[vbase + (size_t)row * SEQ + kr0 + g * 8]);
            }
            CP_COMMIT();
            CP_WAIT0();
            __syncthreads();   // new data visible to all warps
        }
    }

    // Epilogue: unnormalized partials + (m, l)
    const size_t segrow = ((size_t)b * MAXSEG + s) * SEQ + qr0 + w * 16 + lq;
#pragma unroll
    for (int nt = 0; nt < 8; nt++) {
        int cc = nt * 8 + lr * 2;
        *(float2*)&g_pacc[segrow * HD + cc] = make_float2(O[nt][0], O[nt][1]);
        *(float2*)&g_pacc[(segrow + 8) * HD + cc] = make_float2(O[nt][2], O[nt][3]);
    }
    if (lr == 0) {
        g_pm[segrow] = m0;     g_pl[segrow] = l0;
        g_pm[segrow + 8] = m1; g_pl[segrow + 8] = l1;
    }
}

// ---------------------------------------------------------------------------
// Kernel 3: combine split-KV partials and normalize (R7 float4 version).
// Block = 256 threads = 16 rows x 16 col-groups of float4. Grid = (SEQ/16, B).
// ---------------------------------------------------------------------------
__global__ __launch_bounds__(256) void combine_kernel(float* __restrict__ out)
{
    const int b   = blockIdx.y;
    const int row = blockIdx.x * 16 + (threadIdx.x >> 4);
    const int c4  = (threadIdx.x & 15) * 4;
    const int i   = row >> 6;
    const int nseg = (i + CH) >> 3;

    const size_t base = (size_t)b * MAXSEG * SEQ + row;

    float M = -1e30f;
#pragma unroll 4
    for (int s = 0; s < nseg; s++)
        M = fmaxf(M, g_pm[base + (size_t)s * SEQ]);

    float L = 0.f;
    float ax = 0.f, ay = 0.f, az = 0.f, aw = 0.f;
#pragma unroll 4
    for (int s = 0; s < nseg; s++) {
        size_t idx = base + (size_t)s * SEQ;
        float wgt = __expf(g_pm[idx] - M);
        L = fmaf(wgt, g_pl[idx], L);
        float4 p = *(const float4*)&g_pacc[idx * HD + c4];
        ax = fmaf(wgt, p.x, ax);
        ay = fmaf(wgt, p.y, ay);
        az = fmaf(wgt, p.z, az);
        aw = fmaf(wgt, p.w, aw);
    }

    const float inv = 1.f / L;
    *(float4*)&out[((size_t)b * SEQ + row) * HD + c4] =
        make_float4(ax * inv, ay * inv, az * inv, aw * inv);
}

// ---------------------------------------------------------------------------
// Launch: inputs in metadata order x, Wk, Wq, Wv. Output [B,S,H] fp32.
// ---------------------------------------------------------------------------
extern "C" void kernel_launch(void* const* d_in, const int* in_sizes, int n_in,
                              void* d_out, int out_size)
{
    const float* x  = (const float*)d_in[0];
    const float* Wk = (const float*)d_in[1];
    const float* Wq = (const float*)d_in[2];
    const float* Wv = (const float*)d_in[3];
    float* out = (float*)d_out;

    wprep_kernel<<<192, 256>>>(Wq, Wk, Wv);

    cudaFuncSetAttribute(qkv_mma_kernel,
                         cudaFuncAttributeMaxDynamicSharedMemorySize, QKV_SM);
    qkv_mma_kernel<<<ROWS / 64, 256, QKV_SM>>>(x);

    cudaFuncSetAttribute(attn_kernel,
                         cudaFuncAttributeMaxDynamicSharedMemorySize, ATTN_SM);
    attn_kernel<<<dim3(SEG_PER_BATCH, BSZ), 128, ATTN_SM>>>();

    combine_kernel<<<dim3(SEQ / 16, BSZ), 256>>>(out);
}

// round 11
// speedup vs baseline: 1.0453x; 1.0067x over previous
#include <cuda_runtime.h>
#include <cuda_bf16.h>
#include <math.h>
#include <cstdint>

// Problem constants
#define BSZ 4
#define SEQ 4096
#define EMB 1024
#define HD  64
#define ROWS (BSZ * SEQ)

// KV-split chunking for attention
#define CH 8
#define MAXSEG 8
#define SEG_PER_BATCH 288

// Padded smem row stride: 72 bf16 = 144 bytes
#define SSTR 144

// ---------------------------------------------------------------------------
// Scratch (allocation-free: __device__ globals)
// ---------------------------------------------------------------------------
__device__ __nv_bfloat16 g_qh[ROWS * HD];   // Q * 2^-5, bf16 hi
__device__ __nv_bfloat16 g_ql[ROWS * HD];   // residual lo
__device__ __nv_bfloat16 g_kh[ROWS * HD];
__device__ __nv_bfloat16 g_kl[ROWS * HD];
__device__ __nv_bfloat16 g_vth[(size_t)BSZ * HD * SEQ];  // V^T: [b][h][token]
__device__ __nv_bfloat16 g_vtl[(size_t)BSZ * HD * SEQ];
__device__ __nv_bfloat16 g_wth[192 * EMB];  // W^T hi: [n(Q|K|V)][k]
__device__ __nv_bfloat16 g_wtl[192 * EMB];
__device__ float g_pacc[(size_t)BSZ * MAXSEG * SEQ * HD];
__device__ float g_pm[BSZ * MAXSEG * SEQ];
__device__ float g_pl[BSZ * MAXSEG * SEQ];

// ---------------------------------------------------------------------------
// Helpers
// ---------------------------------------------------------------------------
__device__ __forceinline__ uint32_t smem_u32(const void* p) {
    uint32_t a;
    asm("{ .reg .u64 t; cvta.to.shared.u64 t, %1; cvt.u32.u64 %0, t; }"
        : "=r"(a) : "l"(p));
    return a;
}
__device__ __forceinline__ void cp16(uint32_t dst_s, const void* src) {
    asm volatile("cp.async.cg.shared.global [%0], [%1], 16;\n" :: "r"(dst_s), "l"(src));
}
#define CP_COMMIT() asm volatile("cp.async.commit_group;\n" ::: "memory")
#define CP_WAIT0()  asm volatile("cp.async.wait_group 0;\n" ::: "memory")

// m16n8k16 bf16 MMA, fp32 accumulate in-place
__device__ __forceinline__ void mma_bf16(float* d, const uint32_t* a, const uint32_t* b) {
    asm volatile(
        "mma.sync.aligned.m16n8k16.row.col.f32.bf16.bf16.f32 "
        "{%0,%1,%2,%3}, {%4,%5,%6,%7}, {%8,%9}, {%0,%1,%2,%3};\n"
        : "+f"(d[0]), "+f"(d[1]), "+f"(d[2]), "+f"(d[3])
        : "r"(a[0]), "r"(a[1]), "r"(a[2]), "r"(a[3]), "r"(b[0]), "r"(b[1]));
}

// ldmatrix x4: four 8x8 b16 matrices, row addresses from lanes 0-31
__device__ __forceinline__ void ldsm_x4(uint32_t& d0, uint32_t& d1,
                                        uint32_t& d2, uint32_t& d3, uint32_t addr) {
    asm volatile("ldmatrix.sync.aligned.m8n8.x4.shared.b16 {%0,%1,%2,%3}, [%4];"
        : "=r"(d0), "=r"(d1), "=r"(d2), "=r"(d3) : "r"(addr));
}

// Split two floats into packed bf16x2 hi + packed bf16x2 lo
__device__ __forceinline__ void split2(float x0, float x1, uint32_t& hi, uint32_t& lo) {
    __nv_bfloat16 h0 = __float2bfloat16(x0);
    __nv_bfloat16 h1 = __float2bfloat16(x1);
    __nv_bfloat162 hh = __halves2bfloat162(h0, h1);
    hi = *(uint32_t*)&hh;
    __nv_bfloat162 ll = __floats2bfloat162_rn(x0 - __bfloat162float(h0),
                                              x1 - __bfloat162float(h1));
    lo = *(uint32_t*)&ll;
}

// ---------------------------------------------------------------------------
// Kernel 0: W^T -> bf16 hi/lo split. [192][1024]
// ---------------------------------------------------------------------------
__global__ __launch_bounds__(256) void wprep_kernel(
    const float* __restrict__ Wq, const float* __restrict__ Wk,
    const float* __restrict__ Wv)
{
    const int n = blockIdx.x;
    const int m = n >> 6;
    const int h = n & 63;
    const float* W = (m == 0) ? Wq : (m == 1) ? Wk : Wv;
    for (int k = threadIdx.x; k < EMB; k += 256) {
        float v = W[(size_t)k * HD + h];
        __nv_bfloat16 hi = __float2bfloat16(v);
        g_wth[(size_t)n * EMB + k] = hi;
        g_wtl[(size_t)n * EMB + k] = __float2bfloat16(v - __bfloat162float(hi));
    }
}

// ---------------------------------------------------------------------------
// Kernel 1: QKV projection via split-bf16 mma.sync.
// Changes vs R10: A-frags and B-frags loaded via ldmatrix.x4.
// ---------------------------------------------------------------------------
#define XH_OFF 0
#define XL_OFF 9216
#define WH_OFF 18432
#define WL_OFF 46080
#define QKV_SM 73728

__global__ __launch_bounds__(256) void qkv_mma_kernel(const float* __restrict__ x)
{
    extern __shared__ char smc[];
    const uint32_t sb = smem_u32(smc);
    const int tid  = threadIdx.x;
    const int wid  = tid >> 5;
    const int lane = tid & 31;
    const int wr   = wid >> 1;
    const int wc   = wid & 1;
    const int r0   = blockIdx.x * 64;
    const int lq   = lane >> 2;
    const int lr   = lane & 3;

    // ldmatrix lane maps:
    // A (row-major 16x16): mats {0,1} = rows 0-7/8-15 @ k-byte 0; {2,3} @ +16
    const int arow = (((lane >> 3) & 1) << 3) + (lane & 7);
    const int akb  = (lane >> 4) << 4;
    // B (n-major rows): mats {0,1} = rows 0-7 @ bytes {0,16}; {2,3} = rows 8-15
    const int mrow = ((lane >> 4) << 3) + (lane & 7);
    const int mkb  = ((lane >> 3) & 1) << 4;

    float acc[12][4];
#pragma unroll
    for (int nt = 0; nt < 12; nt++)
#pragma unroll
        for (int q = 0; q < 4; q++) acc[nt][q] = 0.f;

    for (int c = 0; c < 16; c++) {
        const int k0 = c * 64;
        __syncthreads();   // previous chunk's consumers done

        // stage x chunk (fp32 -> bf16 hi/lo)
#pragma unroll
        for (int it = 0; it < 2; it++) {
            int cid = tid + it * 256;
            int row = cid >> 3, g = cid & 7;
            const float* src = x + (size_t)(r0 + row) * EMB + k0 + g * 8;
            float4 f0 = *(const float4*)src;
            float4 f1 = *(const float4*)(src + 4);
            uint32_t h[4], l[4];
            split2(f0.x, f0.y, h[0], l[0]);
            split2(f0.z, f0.w, h[1], l[1]);
            split2(f1.x, f1.y, h[2], l[2]);
            split2(f1.z, f1.w, h[3], l[3]);
            *(uint4*)(smc + XH_OFF + row * SSTR + g * 16) = *(uint4*)h;
            *(uint4*)(smc + XL_OFF + row * SSTR + g * 16) = *(uint4*)l;
        }
        // stage W^T chunk via cp.async
#pragma unroll
        for (int it = 0; it < 6; it++) {
            int cid = tid + it * 256;
            int row = cid >> 3, g = cid & 7;
            size_t so = (size_t)row * EMB + k0 + g * 8;
            cp16(sb + WH_OFF + row * SSTR + g * 16, &g_wth[so]);
            cp16(sb + WL_OFF + row * SSTR + g * 16, &g_wtl[so]);
        }
        CP_COMMIT();
        CP_WAIT0();
        __syncthreads();

        // 4 k16 steps, fragments via ldmatrix
#pragma unroll
        for (int ks = 0; ks < 4; ks++) {
            const int ksb = ks * 32;
            uint32_t aH[4], aL[4];
            {
                uint32_t ra = (uint32_t)((wr * 16 + arow) * SSTR + ksb + akb);
                ldsm_x4(aH[0], aH[1], aH[2], aH[3], sb + XH_OFF + ra);
                ldsm_x4(aL[0], aL[1], aL[2], aL[3], sb + XL_OFF + ra);
            }
#pragma unroll
            for (int nt2 = 0; nt2 < 6; nt2++) {
                uint32_t rowb = (uint32_t)((wc * 96 + nt2 * 16 + mrow) * SSTR + ksb + mkb);
                uint32_t bHa[2], bHb[2], bLa[2], bLb[2];
                ldsm_x4(bHa[0], bHa[1], bHb[0], bHb[1], sb + WH_OFF + rowb);
                ldsm_x4(bLa[0], bLa[1], bLb[0], bLb[1], sb + WL_OFF + rowb);
                mma_bf16(acc[nt2 * 2],     aH, bHa);
                mma_bf16(acc[nt2 * 2],     aH, bLa);
                mma_bf16(acc[nt2 * 2],     aL, bHa);
                mma_bf16(acc[nt2 * 2 + 1], aH, bHb);
                mma_bf16(acc[nt2 * 2 + 1], aH, bLb);
                mma_bf16(acc[nt2 * 2 + 1], aL, bHb);
            }
        }
    }

    // Epilogue: emit Q (scaled, split), K (split), V^T (split)
    const int rbase = r0 + wr * 16 + lq;
    const float scale = 0.03125f;  // exact power of 2
#pragma unroll
    for (int nt = 0; nt < 12; nt++) {
        int cc = wc * 96 + nt * 8 + lr * 2;
#pragma unroll
        for (int hh = 0; hh < 2; hh++) {
            int row = rbase + 8 * hh;
            float v0 = acc[nt][2 * hh], v1 = acc[nt][2 * hh + 1];
            if (cc < 64) {
                uint32_t hi, lo;
                split2(v0 * scale, v1 * scale, hi, lo);
                *(uint32_t*)&g_qh[(size_t)row * HD + cc] = hi;
                *(uint32_t*)&g_ql[(size_t)row * HD + cc] = lo;
            } else if (cc < 128) {
                uint32_t hi, lo;
                split2(v0, v1, hi, lo);
                *(uint32_t*)&g_kh[(size_t)row * HD + cc - 64] = hi;
                *(uint32_t*)&g_kl[(size_t)row * HD + cc - 64] = lo;
            } else {
                int h = cc - 128;
                int b = row >> 12;
                int tok = row & (SEQ - 1);
                size_t base = (size_t)b * HD * SEQ + tok;
                __nv_bfloat16 h0 = __float2bfloat16(v0);
                __nv_bfloat16 h1 = __float2bfloat16(v1);
                g_vth[base + (size_t)h * SEQ]       = h0;
                g_vth[base + (size_t)(h + 1) * SEQ] = h1;
                g_vtl[base + (size_t)h * SEQ]       = __float2bfloat16(v0 - __bfloat162float(h0));
                g_vtl[base + (size_t)(h + 1) * SEQ] = __float2bfloat16(v1 - __bfloat162float(h1));
            }
        }
    }
}

// ---------------------------------------------------------------------------
// Kernel 2: causal flash attention, split-KV, split-bf16 mma.sync.
// R10 structure; ONE change: Q A-fragments hoisted into registers via
// ldmatrix once per CTA (loop-invariant across k-tiles).
// ---------------------------------------------------------------------------
#define QH_OFF 0
#define QL_OFF 9216
#define KH_OFF 18432
#define KL_OFF 27648
#define VH_OFF 36864
#define VL_OFF 46080
#define ATTN_SM 55296

__global__ __launch_bounds__(128, 3) void attn_kernel()
{
    extern __shared__ char smc[];
    const uint32_t sb = smem_u32(smc);
    const int tid  = threadIdx.x;
    const int w    = tid >> 5;
    const int lane = tid & 31;
    const int lq   = lane >> 2;
    const int lr   = lane & 3;
    const int b    = blockIdx.y;

    // ldmatrix lane maps (see qkv kernel)
    const int arow = (((lane >> 3) & 1) << 3) + (lane & 7);
    const int akb  = (lane >> 4) << 4;
    const int mrow = ((lane >> 4) << 3) + (lane & 7);
    const int mkb  = ((lane >> 3) & 1) << 4;

    // decode blockIdx.x -> (q-tile i, segment s)
    int fid = blockIdx.x;
    int i = 0, s = 0;
    {
        int accn = 0;
        for (int t = 63; t >= 0; t--) {
            int c = (t + CH) >> 3;
            if (fid < accn + c) { i = t; s = fid - accn; break; }
            accn += c;
        }
    }
    const int T  = i + 1;
    const int j0 = s * CH;
    const int j1 = (j0 + CH < T) ? (j0 + CH) : T;
    const int qr0 = i * 64;

    const size_t tok0  = (size_t)b * SEQ;
    const size_t vbase = (size_t)b * HD * SEQ;

    // stage Q (hi/lo) + first K/V tile
    {
        int kr0 = j0 * 64;
#pragma unroll
        for (int it = 0; it < 4; it++) {
            int cid = tid + it * 128;
            int row = cid >> 3, g = cid & 7;
            cp16(sb + QH_OFF + row * SSTR + g * 16, &g_qh[(tok0 + qr0 + row) * HD + g * 8]);
            cp16(sb + QL_OFF + row * SSTR + g * 16, &g_ql[(tok0 + qr0 + row) * HD + g * 8]);
            cp16(sb + KH_OFF + row * SSTR + g * 16, &g_kh[(tok0 + kr0 + row) * HD + g * 8]);
            cp16(sb + KL_OFF + row * SSTR + g * 16, &g_kl[(tok0 + kr0 + row) * HD + g * 8]);
            cp16(sb + VH_OFF + row * SSTR + g * 16, &g_vth[vbase + (size_t)row * SEQ + kr0 + g * 8]);
            cp16(sb + VL_OFF + row * SSTR + g * 16, &g_vtl[vbase + (size_t)row * SEQ + kr0 + g * 8]);
        }
    }
    CP_COMMIT();
    CP_WAIT0();
    __syncthreads();

    // hoist Q A-fragments into registers (loop-invariant)
    uint32_t qfh[4][4], qfl[4][4];
#pragma unroll
    for (int kf = 0; kf < 4; kf++) {
        uint32_t ra = (uint32_t)((w * 16 + arow) * SSTR + kf * 32 + akb);
        ldsm_x4(qfh[kf][0], qfh[kf][1], qfh[kf][2], qfh[kf][3], sb + QH_OFF + ra);
        ldsm_x4(qfl[kf][0], qfl[kf][1], qfl[kf][2], qfl[kf][3], sb + QL_OFF + ra);
    }

    float O[8][4];
#pragma unroll
    for (int nt = 0; nt < 8; nt++)
#pragma unroll
        for (int q = 0; q < 4; q++) O[nt][q] = 0.f;
    float m0 = -1e30f, m1 = -1e30f, l0 = 0.f, l1 = 0.f;

    for (int j = j0; j < j1; j++) {
        // ---- S = Q K^T ----
        float S[8][4];
#pragma unroll
        for (int nt = 0; nt < 8; nt++)
#pragma unroll
            for (int q = 0; q < 4; q++) S[nt][q] = 0.f;

#pragma unroll
        for (int kf = 0; kf < 4; kf++) {
            const int kfb = kf * 32;
#pragma unroll
            for (int nt2 = 0; nt2 < 4; nt2++) {
                uint32_t rowb = (uint32_t)((nt2 * 16 + mrow) * SSTR + kfb + mkb);
                uint32_t bHa[2], bHb[2], bLa[2], bLb[2];
                ldsm_x4(bHa[0], bHa[1], bHb[0], bHb[1], sb + KH_OFF + rowb);
                ldsm_x4(bLa[0], bLa[1], bLb[0], bLb[1], sb + KL_OFF + rowb);
                mma_bf16(S[nt2 * 2],     qfh[kf], bHa);
                mma_bf16(S[nt2 * 2],     qfh[kf], bLa);
                mma_bf16(S[nt2 * 2],     qfl[kf], bHa);
                mma_bf16(S[nt2 * 2 + 1], qfh[kf], bHb);
                mma_bf16(S[nt2 * 2 + 1], qfh[kf], bLb);
                mma_bf16(S[nt2 * 2 + 1], qfl[kf], bHb);
            }
        }

        // causal mask (diagonal tile only)
        if (j == i) {
            int r0g = w * 16 + lq;
#pragma unroll
            for (int nt = 0; nt < 8; nt++) {
                int c0 = nt * 8 + lr * 2;
                if (c0 > r0g)         S[nt][0] = -1e30f;
                if (c0 + 1 > r0g)     S[nt][1] = -1e30f;
                if (c0 > r0g + 8)     S[nt][2] = -1e30f;
                if (c0 + 1 > r0g + 8) S[nt][3] = -1e30f;
            }
        }

        // ---- online softmax ----
        float mn0 = -1e30f, mn1 = -1e30f;
#pragma unroll
        for (int nt = 0; nt < 8; nt++) {
            mn0 = fmaxf(mn0, fmaxf(S[nt][0], S[nt][1]));
            mn1 = fmaxf(mn1, fmaxf(S[nt][2], S[nt][3]));
        }
        mn0 = fmaxf(mn0, __shfl_xor_sync(0xffffffffu, mn0, 1));
        mn0 = fmaxf(mn0, __shfl_xor_sync(0xffffffffu, mn0, 2));
        mn1 = fmaxf(mn1, __shfl_xor_sync(0xffffffffu, mn1, 1));
        mn1 = fmaxf(mn1, __shfl_xor_sync(0xffffffffu, mn1, 2));
        float mc0 = fmaxf(m0, mn0), mc1 = fmaxf(m1, mn1);
        float al0 = __expf(m0 - mc0), al1 = __expf(m1 - mc1);
        m0 = mc0; m1 = mc1;
        float rs0 = 0.f, rs1 = 0.f;
#pragma unroll
        for (int nt = 0; nt < 8; nt++) {
            S[nt][0] = __expf(S[nt][0] - mc0);
            S[nt][1] = __expf(S[nt][1] - mc0);
            S[nt][2] = __expf(S[nt][2] - mc1);
            S[nt][3] = __expf(S[nt][3] - mc1);
            rs0 += S[nt][0] + S[nt][1];
            rs1 += S[nt][2] + S[nt][3];
        }
        rs0 += __shfl_xor_sync(0xffffffffu, rs0, 1);
        rs0 += __shfl_xor_sync(0xffffffffu, rs0, 2);
        rs1 += __shfl_xor_sync(0xffffffffu, rs1, 1);
        rs1 += __shfl_xor_sync(0xffffffffu, rs1, 2);
        l0 = l0 * al0 + rs0;
        l1 = l1 * al1 + rs1;
#pragma unroll
        for (int nt = 0; nt < 8; nt++) {
            O[nt][0] *= al0; O[nt][1] *= al0;
            O[nt][2] *= al1; O[nt][3] *= al1;
        }

        // ---- O += P V (P re-packed from S frags; V B-frags via ldmatrix) ----
#pragma unroll
        for (int kf = 0; kf < 4; kf++) {
            uint32_t aPh[4], aPl[4];
            split2(S[2 * kf][0],     S[2 * kf][1],     aPh[0], aPl[0]);
            split2(S[2 * kf][2],     S[2 * kf][3],     aPh[1], aPl[1]);
            split2(S[2 * kf + 1][0], S[2 * kf + 1][1], aPh[2], aPl[2]);
            split2(S[2 * kf + 1][2], S[2 * kf + 1][3], aPh[3], aPl[3]);
            const int kfb = kf * 32;
#pragma unroll
            for (int nt2 = 0; nt2 < 4; nt2++) {
                uint32_t rowb = (uint32_t)((nt2 * 16 + mrow) * SSTR + kfb + mkb);
                uint32_t bHa[2], bHb[2], bLa[2], bLb[2];
                ldsm_x4(bHa[0], bHa[1], bHb[0], bHb[1], sb + VH_OFF + rowb);
                ldsm_x4(bLa[0], bLa[1], bLb[0], bLb[1], sb + VL_OFF + rowb);
                mma_bf16(O[nt2 * 2],     aPh, bHa);
                mma_bf16(O[nt2 * 2],     aPh, bLa);
                mma_bf16(O[nt2 * 2],     aPl, bHa);
                mma_bf16(O[nt2 * 2 + 1], aPh, bHb);
                mma_bf16(O[nt2 * 2 + 1], aPh, bLb);
                mma_bf16(O[nt2 * 2 + 1], aPl, bHb);
            }
        }

        // load next tile into the (single) buffer
        if (j + 1 < j1) {
            __syncthreads();   // all warps done reading K/V
            int kr0 = (j + 1) * 64;
#pragma unroll
            for (int it = 0; it < 4; it++) {
                int cid = tid + it * 128;
                int row = cid >> 3, g = cid & 7;
                cp16(sb + KH_OFF + row * SSTR + g * 16, &g_kh[(tok0 + kr0 + row) * HD + g * 8]);
                cp16(sb + KL_OFF + row * SSTR + g * 16, &g_kl[(tok0 + kr0 + row) * HD + g * 8]);
                cp16(sb + VH_OFF + row * SSTR + g * 16, &g_vth[vbase + (size_t)row * SEQ + kr0 + g * 8]);
                cp16(sb + VL_OFF + row * SSTR + g * 16, &g_vtl[vbase + (size_t)row * SEQ + kr0 + g * 8]);
            }
            CP_COMMIT();
            CP_WAIT0();
            __syncthreads();   // new data visible to all warps
        }
    }

    // Epilogue: unnormalized partials + (m, l)
    const size_t segrow = ((size_t)b * MAXSEG + s) * SEQ + qr0 + w * 16 + lq;
#pragma unroll
    for (int nt = 0; nt < 8; nt++) {
        int cc = nt * 8 + lr * 2;
        *(float2*)&g_pacc[segrow * HD + cc] = make_float2(O[nt][0], O[nt][1]);
        *(float2*)&g_pacc[(segrow + 8) * HD + cc] = make_float2(O[nt][2], O[nt][3]);
    }
    if (lr == 0) {
        g_pm[segrow] = m0;     g_pl[segrow] = l0;
        g_pm[segrow + 8] = m1; g_pl[segrow + 8] = l1;
    }
}

// ---------------------------------------------------------------------------
// Kernel 3: combine split-KV partials and normalize (R7/R10 float4 version).
// ---------------------------------------------------------------------------
__global__ __launch_bounds__(256) void combine_kernel(float* __restrict__ out)
{
    const int b   = blockIdx.y;
    const int row = blockIdx.x * 16 + (threadIdx.x >> 4);
    const int c4  = (threadIdx.x & 15) * 4;
    const int i   = row >> 6;
    const int nseg = (i + CH) >> 3;

    const size_t base = (size_t)b * MAXSEG * SEQ + row;

    float M = -1e30f;
#pragma unroll 4
    for (int s = 0; s < nseg; s++)
        M = fmaxf(M, g_pm[base + (size_t)s * SEQ]);

    float L = 0.f;
    float ax = 0.f, ay = 0.f, az = 0.f, aw = 0.f;
#pragma unroll 4
    for (int s = 0; s < nseg; s++) {
        size_t idx = base + (size_t)s * SEQ;
        float wgt = __expf(g_pm[idx] - M);
        L = fmaf(wgt, g_pl[idx], L);
        float4 p = *(const float4*)&g_pacc[idx * HD + c4];
        ax = fmaf(wgt, p.x, ax);
        ay = fmaf(wgt, p.y, ay);
        az = fmaf(wgt, p.z, az);
        aw = fmaf(wgt, p.w, aw);
    }

    const float inv = 1.f / L;
    *(float4*)&out[((size_t)b * SEQ + row) * HD + c4] =
        make_float4(ax * inv, ay * inv, az * inv, aw * inv);
}

// ---------------------------------------------------------------------------
// Launch: inputs in metadata order x, Wk, Wq, Wv. Output [B,S,H] fp32.
// ---------------------------------------------------------------------------
extern "C" void kernel_launch(void* const* d_in, const int* in_sizes, int n_in,
                              void* d_out, int out_size)
{
    const float* x  = (const float*)d_in[0];
    const float* Wk = (const float*)d_in[1];
    const float* Wq = (const float*)d_in[2];
    const float* Wv = (const float*)d_in[3];
    float* out = (float*)d_out;

    wprep_kernel<<<192, 256>>>(Wq, Wk, Wv);

    cudaFuncSetAttribute(qkv_mma_kernel,
                         cudaFuncAttributeMaxDynamicSharedMemorySize, QKV_SM);
    qkv_mma_kernel<<<ROWS / 64, 256, QKV_SM>>>(x);

    cudaFuncSetAttribute(attn_kernel,
                         cudaFuncAttributeMaxDynamicSharedMemorySize, ATTN_SM);
    attn_kernel<<<dim3(SEG_PER_BATCH, BSZ), 128, ATTN_SM>>>();

    combine_kernel<<<dim3(SEQ / 16, BSZ), 256>>>(out);
}